// round 15
// baseline (speedup 1.0000x reference)
#include <cuda_runtime.h>
#include <math.h>
#include <stdint.h>

#define S_LEN 2048
#define BATCH 2
#define HID 2048
#define NHEAD 16
#define HDIM 128
#define QKV_N 6144
#define ROWS 4096

// ---------------- scratch (device globals; allocation forbidden) -----------
__device__ uint32_t g_hs_t[(size_t)ROWS * HID];      // tf32 bits of hidden_states
__device__ uint32_t g_wqkv_t[(size_t)QKV_N * HID];   // tf32 bits of w_qkv
__device__ uint32_t g_wd_t[(size_t)HID * HID];       // tf32 bits of w_dense
__device__ uint32_t g_qkv[(size_t)ROWS * QKV_N];     // tf32 bits of qkv
__device__ uint32_t g_vt[(size_t)BATCH * NHEAD * HDIM * S_LEN];  // V transposed
__device__ uint32_t g_ctx_t[(size_t)ROWS * HID];     // tf32 bits of ctx

// ---------------- helpers --------------------------------------------------
__device__ __forceinline__ uint32_t f2tf(float x) {
    uint32_t r; asm("cvt.rna.tf32.f32 %0, %1;" : "=r"(r) : "f"(x)); return r;
}
__device__ __forceinline__ float ex2(float x) {
    float y; asm("ex2.approx.f32 %0, %1;" : "=f"(y) : "f"(x)); return y;
}
__device__ __forceinline__ void mma8(float* c, const uint32_t* a, uint32_t b0, uint32_t b1) {
    asm volatile("mma.sync.aligned.m16n8k8.row.col.f32.tf32.tf32.f32 "
        "{%0,%1,%2,%3},{%4,%5,%6,%7},{%8,%9},{%0,%1,%2,%3};"
        : "+f"(c[0]), "+f"(c[1]), "+f"(c[2]), "+f"(c[3])
        : "r"(a[0]), "r"(a[1]), "r"(a[2]), "r"(a[3]), "r"(b0), "r"(b1));
}
__device__ __forceinline__ void ldsm4(uint32_t* r, uint32_t addr) {
    asm volatile("ldmatrix.sync.aligned.m8n8.x4.shared.b16 {%0,%1,%2,%3}, [%4];"
        : "=r"(r[0]), "=r"(r[1]), "=r"(r[2]), "=r"(r[3]) : "r"(addr));
}
__device__ __forceinline__ void cp16(uint32_t saddr, const void* gptr) {
    asm volatile("cp.async.cg.shared.global [%0], [%1], 16;" :: "r"(saddr), "l"(gptr));
}
__device__ __forceinline__ uint32_t smem_u32(const void* p) {
    uint32_t a;
    asm("{ .reg .u64 t; cvta.to.shared.u64 t, %1; cvt.u32.u64 %0, t; }" : "=r"(a) : "l"(p));
    return a;
}

#define MBAR_INIT(addr, cnt) \
    asm volatile("mbarrier.init.shared.b64 [%0], %1;" :: "r"(addr), "r"(cnt) : "memory")
#define MBAR_ARRIVE(addr) \
    asm volatile("mbarrier.arrive.shared.b64 _, [%0];" :: "r"(addr) : "memory")
#define MBAR_ARRIVE_CPASYNC(addr) \
    asm volatile("cp.async.mbarrier.arrive.noinc.shared.b64 [%0];" :: "r"(addr) : "memory")
#define MBAR_WAIT(addr, par) do {                                               \
    uint32_t _done;                                                             \
    asm volatile("{ .reg .pred p; mbarrier.try_wait.parity.acquire.cta.shared::cta.b64 p, [%1], %2; selp.b32 %0,1,0,p; }" \
        : "=r"(_done) : "r"(addr), "r"(par) : "memory");                        \
    while (!_done) {                                                            \
        asm volatile("{ .reg .pred p; mbarrier.try_wait.parity.acquire.cta.shared::cta.b64 p, [%1], %2, 0x989680; selp.b32 %0,1,0,p; }" \
            : "=r"(_done) : "r"(addr), "r"(par) : "memory");                    \
    }                                                                           \
} while (0)

// ---------------- fp32 -> tf32 conversion kernel ---------------------------
__global__ void cvt_tf32_kernel(const float4* __restrict__ in, uint4* __restrict__ out, int n4) {
    int i = blockIdx.x * blockDim.x + threadIdx.x;
    if (i < n4) {
        float4 v = in[i];
        uint4 o;
        o.x = f2tf(v.x); o.y = f2tf(v.y); o.z = f2tf(v.z); o.w = f2tf(v.w);
        out[i] = o;
    }
}

// ---------------- V transpose: qkv V columns -> vt[b][h][hd][S] -------------
__global__ __launch_bounds__(256, 4)
void transpose_v(const uint32_t* __restrict__ qkv, uint32_t* __restrict__ vt)
{
    __shared__ uint32_t tile[32][33];
    const int st = blockIdx.x;
    const int ht = blockIdx.y;
    const int bh = blockIdx.z;
    const int head = bh & 15, bb = bh >> 4;
    const int tx = threadIdx.x & 31, ty = threadIdx.x >> 5;

#pragma unroll
    for (int rr = 0; rr < 4; rr++) {
        int s = st * 32 + ty + rr * 8;
        int hd = ht * 32 + tx;
        tile[ty + rr * 8][tx] =
            qkv[((size_t)s * BATCH + bb) * QKV_N + head * 384 + 2 * HDIM + hd];
    }
    __syncthreads();
#pragma unroll
    for (int rr = 0; rr < 4; rr++) {
        int hd = ht * 32 + ty + rr * 8;
        int s = st * 32 + tx;
        vt[((size_t)(bb * NHEAD + head) * HDIM + hd) * S_LEN + s] = tile[tx][ty + rr * 8];
    }
}

// ---------------- tf32 GEMM: unchanged from R11/R12/R13 ---------------------
#define GBM 128
#define GBN 128
#define GBK 32
#define SLD 36
#define TSZ (128 * SLD)
#define GEMM_SMEM_BYTES (3 * 2 * TSZ * 4)       // 110592
#define GTHREADS 256

__global__ __launch_bounds__(GTHREADS, 2)
void gemm_tf32(const uint32_t* __restrict__ A, const uint32_t* __restrict__ B,
               const float* __restrict__ bias, uint32_t* __restrict__ C,
               int M, int N, int K, int add_bias, int out_tf32)
{
    extern __shared__ uint32_t sm[];
    __shared__ uint64_t bars[6];

    const int tid = threadIdx.x;
    const int lane = tid & 31, warp = tid >> 5;
    const int g = lane >> 2, tg = lane & 3;
    const int wm = warp >> 2, wn = warp & 3;
    const int m0 = blockIdx.y * GBM, n0 = blockIdx.x * GBN;
    const uint32_t smb = smem_u32(sm);
    const uint32_t barb = smem_u32(bars);
#define FULLB(s)  (barb + 8u * (uint32_t)(s))
#define EMPTYB(s) (barb + 24u + 8u * (uint32_t)(s))

    if (tid == 0) {
#pragma unroll
        for (int s = 0; s < 3; s++) {
            MBAR_INIT(FULLB(s), GTHREADS);
            MBAR_INIT(EMPTYB(s), GTHREADS);
        }
    }
    __syncthreads();

    const uint32_t aRowOff = (uint32_t)(((wm * 64 + (lane & 15)) * SLD + (lane >> 4) * 4) * 4);
    const uint32_t bRowOff = (uint32_t)(((wn * 32 + ((lane >> 4) & 1) * 8 + (lane & 7)) * SLD
                                         + ((lane >> 3) & 1) * 4) * 4);

    float c[4][4][4];
#pragma unroll
    for (int i = 0; i < 4; i++)
#pragma unroll
        for (int j = 0; j < 4; j++)
#pragma unroll
            for (int q = 0; q < 4; q++) c[i][j][q] = 0.f;

    auto load_stage = [&](int it) {
        const int buf = it % 3;
        uint32_t ab = smb + (uint32_t)(buf * 2 * TSZ) * 4;
        uint32_t bb = ab + (uint32_t)TSZ * 4;
        const int k0 = it * GBK;
#pragma unroll
        for (int t = 0; t < 4; t++) {
            int fid = tid + GTHREADS * t;
            int r = fid >> 3, c4 = (fid & 7) * 4;
            cp16(ab + (uint32_t)(r * SLD + c4) * 4, A + (size_t)(m0 + r) * K + k0 + c4);
            cp16(bb + (uint32_t)(r * SLD + c4) * 4, B + (size_t)(n0 + r) * K + k0 + c4);
        }
        MBAR_ARRIVE_CPASYNC(FULLB(buf));
    };

    const int NI = K / GBK;
    load_stage(0);
    load_stage(1);

    for (int it = 0; it < NI; it++) {
        const int nx = it + 2;
        if (nx < NI) {
            const int qn = nx % 3, rn = nx / 3;
            if (rn >= 1) MBAR_WAIT(EMPTYB(qn), (uint32_t)((rn - 1) & 1));
            load_stage(nx);
        }
        const int q = it % 3;
        MBAR_WAIT(FULLB(q), (uint32_t)((it / 3) & 1));

        const uint32_t aBase = smb + (uint32_t)(q * 2 * TSZ) * 4 + aRowOff;
        const uint32_t bBase = smb + (uint32_t)(q * 2 * TSZ + TSZ) * 4 + bRowOff;
#pragma unroll
        for (int kk = 0; kk < 4; kk++) {
            uint32_t a[4][4], bv[2][4];
#pragma unroll
            for (int i = 0; i < 4; i++)
                ldsm4(a[i], aBase + (uint32_t)(i * 16 * SLD) * 4 + kk * 32);
#pragma unroll
            for (int jp = 0; jp < 2; jp++)
                ldsm4(bv[jp], bBase + (uint32_t)(jp * 16 * SLD) * 4 + kk * 32);
#pragma unroll
            for (int jp = 0; jp < 2; jp++)
#pragma unroll
                for (int i = 0; i < 4; i++) {
                    mma8(c[i][2 * jp],     a[i], bv[jp][0], bv[jp][1]);
                    mma8(c[i][2 * jp + 1], a[i], bv[jp][2], bv[jp][3]);
                }
        }
        MBAR_ARRIVE(EMPTYB(q));
    }

#pragma unroll
    for (int i = 0; i < 4; i++) {
        int row = m0 + wm * 64 + i * 16 + g;
#pragma unroll
        for (int j = 0; j < 4; j++) {
            int col = n0 + wn * 32 + j * 8 + 2 * tg;
            float b0 = add_bias ? bias[col] : 0.f;
            float b1 = add_bias ? bias[col + 1] : 0.f;
            float v00 = c[i][j][0] + b0, v01 = c[i][j][1] + b1;
            float v10 = c[i][j][2] + b0, v11 = c[i][j][3] + b1;
            uint2 r0, r1;
            if (out_tf32) {
                r0.x = f2tf(v00); r0.y = f2tf(v01);
                r1.x = f2tf(v10); r1.y = f2tf(v11);
            } else {
                r0.x = __float_as_uint(v00); r0.y = __float_as_uint(v01);
                r1.x = __float_as_uint(v10); r1.y = __float_as_uint(v11);
            }
            *(uint2*)(C + (size_t)row * N + col) = r0;
            *(uint2*)(C + (size_t)(row + 8) * N + col) = r1;
        }
    }
#undef FULLB
#undef EMPTYB
}

// ---------------- tf32 flash attention, KCH=64, software-pipelined ----------
// Per-iter order: softmax(kt) -> P -> PV(kt) -> arrive -> load(kt+2)
// -> wait_full(kt+1) -> QK(kt+1).  PV(kt)+QK(kt+1) form one contiguous MMA
// block per warp; softmax is the only tensor gap.
#define AQ_LD 132
#define AK_LD 132
#define VT_LD 68
#define AP_LD 68
#define KCH 64
#define KVBUF (KCH * AK_LD + HDIM * VT_LD)      // 17152 words
#define ATT_WORDS (2 * KVBUF + 128 * AP_LD)     // 43008
#define ATT_BYTES (ATT_WORDS * 4)               // 172032

__global__ __launch_bounds__(256, 1)
void attn_tf32(const uint32_t* __restrict__ qkv, const uint32_t* __restrict__ vt,
               uint32_t* __restrict__ ctx)
{
    extern __shared__ uint32_t sm[];
    uint32_t* KV = sm;                           // 2 x KVBUF
    uint32_t* Ps = KV + 2 * KVBUF;
    const uint32_t kvb = smem_u32(KV);
    __shared__ uint64_t abars[4];                // full[0..1], empty[0..1]
    const uint32_t abarb = smem_u32(abars);
#define AFULL(s)  (abarb + 8u * (uint32_t)(s))
#define AEMPTY(s) (abarb + 16u + 8u * (uint32_t)(s))

    const int tid = threadIdx.x, lane = tid & 31, warp = tid >> 5;
    const int g = lane >> 2, tg = lane & 3;
    const int qt = gridDim.x - 1 - blockIdx.x;   // heavy tiles first
    const int head = blockIdx.y, bb = blockIdx.z;
    const int q0 = qt * 128;
    const size_t hoff = (size_t)head * (3 * HDIM);
    const uint32_t* vtp = vt + (size_t)(bb * NHEAD + head) * HDIM * S_LEN;

    if (tid == 0) {
#pragma unroll
        for (int s = 0; s < 2; s++) {
            MBAR_INIT(AFULL(s), 256);
            MBAR_INIT(AEMPTY(s), 256);
        }
    }
    __syncthreads();

    // ldmatrix row offsets
    const uint32_t qRowOff = (uint32_t)(((warp * 16 + (lane & 15)) * AQ_LD + (lane >> 4) * 4) * 4);
    const uint32_t kRowOff = (uint32_t)(((((lane >> 4) & 1) * 8 + (lane & 7)) * AK_LD
                                         + ((lane >> 3) & 1) * 4) * 4);
    const uint32_t vRowOff = (uint32_t)(((((lane >> 4) & 1) * 8 + (lane & 7)) * VT_LD
                                         + ((lane >> 3) & 1) * 4) * 4);
    const uint32_t pRowOff = (uint32_t)(((warp * 16 + (lane & 15)) * AP_LD + (lane >> 4) * 4) * 4);
    const uint32_t pBase = smem_u32(Ps) + pRowOff;

    auto load_kv = [&](int kt) {
        const int b = kt & 1;
        const uint32_t kb = kvb + (uint32_t)(b * KVBUF) * 4;
        const uint32_t vb = kb + (uint32_t)(KCH * AK_LD) * 4;
        const int kr0 = kt * KCH;
#pragma unroll
        for (int t = 0; t < 8; t++) {            // K: 64 rows x 32 16B-chunks
            int fid = tid + 256 * t;
            int r = fid >> 5, c4 = (fid & 31) * 4;
            const uint32_t* s = qkv + ((size_t)(kr0 + r) * BATCH + bb) * QKV_N + hoff + HDIM + c4;
            cp16(kb + (uint32_t)(r * AK_LD + c4) * 4, s);
        }
#pragma unroll
        for (int t = 0; t < 8; t++) {            // V^T: 128 rows x 16 chunks
            int fid = tid + 256 * t;
            int r = fid >> 4, c4 = (fid & 15) * 4;
            cp16(vb + (uint32_t)(r * VT_LD + c4) * 4, vtp + (size_t)r * S_LEN + kr0 + c4);
        }
        MBAR_ARRIVE_CPASYNC(AFULL(b));
    };

    // prologue: stage Q into KV buffer 1 (dead after fragment hoist)
    {
        const uint32_t qstage = kvb + (uint32_t)KVBUF * 4;
#pragma unroll
        for (int t = 0; t < 16; t++) {
            int fid = tid + 256 * t;
            int r = fid >> 5, c4 = (fid & 31) * 4;
            const uint32_t* s = qkv + ((size_t)(q0 + r) * BATCH + bb) * QKV_N + hoff + c4;
            cp16(qstage + (uint32_t)(r * AQ_LD + c4) * 4, s);
        }
        asm volatile("cp.async.commit_group;" ::: "memory");
        asm volatile("cp.async.wait_group 0;" ::: "memory");
        __syncthreads();
    }

    uint32_t qf[16][4];
    {
        const uint32_t qBase = kvb + (uint32_t)KVBUF * 4 + qRowOff;
#pragma unroll
        for (int kk = 0; kk < 16; kk++) ldsm4(qf[kk], qBase + kk * 32);
    }
    __syncthreads();                             // all hoists done before buf1 overwrite

    const int nkt = 2 * qt + 2;
    const int lastRow = q0 + warp * 16 + 15;
    const int rowg = q0 + warp * 16 + g;

    float s[8][4];
    auto qk_mma = [&](int b) {
        const uint32_t kBase = kvb + (uint32_t)(b * KVBUF) * 4 + kRowOff;
#pragma unroll
        for (int j = 0; j < 8; j++)
#pragma unroll
            for (int q = 0; q < 4; q++) s[j][q] = 0.f;
#pragma unroll
        for (int kk = 0; kk < 16; kk++) {
            uint32_t bv[4][4];
#pragma unroll
            for (int jt = 0; jt < 4; jt++)
                ldsm4(bv[jt], kBase + (uint32_t)(jt * 16 * AK_LD) * 4 + kk * 32);
#pragma unroll
            for (int jt = 0; jt < 4; jt++) {
                mma8(s[2 * jt],     qf[kk], bv[jt][0], bv[jt][1]);
                mma8(s[2 * jt + 1], qf[kk], bv[jt][2], bv[jt][3]);
            }
        }
    };

    load_kv(0);
    MBAR_WAIT(AFULL(0), 0u);
    qk_mma(0);                                   // all warps active at kt=0
    load_kv(1);                                  // buffer 1 first fill

    float o[16][4];
#pragma unroll
    for (int j = 0; j < 16; j++)
#pragma unroll
        for (int q = 0; q < 4; q++) o[j][q] = 0.f;
    float m0r = -1e30f, m1r = -1e30f, l0r = 0.f, l1r = 0.f;
    const float scale2 = 0.08838834764831845f * 1.4426950408889634f;
    const float MASK2 = -14426.95f;              // -10000 * log2(e)

    for (int kt = 0; kt < nkt; kt++) {
        const int b = kt & 1;
        const int kr0 = kt * KCH;
        const bool act = (kr0 <= lastRow);

        if (act) {
            // mask + scale (exp2 domain)
#pragma unroll
            for (int j = 0; j < 8; j++) {
                int cb = kr0 + j * 8 + 2 * tg;
                s[j][0] = (cb     > rowg)     ? MASK2 : s[j][0] * scale2;
                s[j][1] = (cb + 1 > rowg)     ? MASK2 : s[j][1] * scale2;
                s[j][2] = (cb     > rowg + 8) ? MASK2 : s[j][2] * scale2;
                s[j][3] = (cb + 1 > rowg + 8) ? MASK2 : s[j][3] * scale2;
            }
            {
                float ml = -1e30f;
#pragma unroll
                for (int j = 0; j < 8; j++) ml = fmaxf(ml, fmaxf(s[j][0], s[j][1]));
                ml = fmaxf(ml, __shfl_xor_sync(0xffffffffu, ml, 1));
                ml = fmaxf(ml, __shfl_xor_sync(0xffffffffu, ml, 2));
                float mn = fmaxf(m0r, ml);
                float corr = ex2(m0r - mn);
                float ps = 0.f;
#pragma unroll
                for (int j = 0; j < 8; j++) {
                    s[j][0] = ex2(s[j][0] - mn);
                    s[j][1] = ex2(s[j][1] - mn);
                    ps += s[j][0] + s[j][1];
                }
                ps += __shfl_xor_sync(0xffffffffu, ps, 1);
                ps += __shfl_xor_sync(0xffffffffu, ps, 2);
                l0r = l0r * corr + ps; m0r = mn;
#pragma unroll
                for (int j = 0; j < 16; j++) { o[j][0] *= corr; o[j][1] *= corr; }
            }
            {
                float ml = -1e30f;
#pragma unroll
                for (int j = 0; j < 8; j++) ml = fmaxf(ml, fmaxf(s[j][2], s[j][3]));
                ml = fmaxf(ml, __shfl_xor_sync(0xffffffffu, ml, 1));
                ml = fmaxf(ml, __shfl_xor_sync(0xffffffffu, ml, 2));
                float mn = fmaxf(m1r, ml);
                float corr = ex2(m1r - mn);
                float ps = 0.f;
#pragma unroll
                for (int j = 0; j < 8; j++) {
                    s[j][2] = ex2(s[j][2] - mn);
                    s[j][3] = ex2(s[j][3] - mn);
                    ps += s[j][2] + s[j][3];
                }
                ps += __shfl_xor_sync(0xffffffffu, ps, 1);
                ps += __shfl_xor_sync(0xffffffffu, ps, 2);
                l1r = l1r * corr + ps; m1r = mn;
#pragma unroll
                for (int j = 0; j < 16; j++) { o[j][2] *= corr; o[j][3] *= corr; }
            }
            // store P (tf32 bits)
#pragma unroll
            for (int j = 0; j < 8; j++) {
                uint32_t* p0 = Ps + (warp * 16 + g) * AP_LD + j * 8 + 2 * tg;
                uint2 w0 = { f2tf(s[j][0]), f2tf(s[j][1]) };
                uint2 w1 = { f2tf(s[j][2]), f2tf(s[j][3]) };
                *(uint2*)p0 = w0;
                *(uint2*)(p0 + 8 * AP_LD) = w1;
            }
        }
        __syncwarp();
        if (act) {
            // O += P @ V via ldmatrix on V^T (k = 64)
            const uint32_t vBase = kvb + (uint32_t)(b * KVBUF + KCH * AK_LD) * 4 + vRowOff;
#pragma unroll
            for (int kk = 0; kk < 8; kk++) {
                uint32_t a[4];
                ldsm4(a, pBase + kk * 32);
#pragma unroll
                for (int jp = 0; jp < 8; jp++) {
                    uint32_t v[4];
                    ldsm4(v, vBase + (uint32_t)(jp * 16 * VT_LD) * 4 + kk * 32);
                    mma8(o[2 * jp],     a, v[0], v[1]);
                    mma8(o[2 * jp + 1], a, v[2], v[3]);
                }
            }
        }
        MBAR_ARRIVE(AEMPTY(b));
        if (kt + 2 < nkt) {
            MBAR_WAIT(AEMPTY(b), (uint32_t)((kt >> 1) & 1));
            load_kv(kt + 2);
        }
        if (kt + 1 < nkt && (kt + 1) * KCH <= lastRow) {
            MBAR_WAIT(AFULL((kt + 1) & 1), (uint32_t)(((kt + 1) >> 1) & 1));
            qk_mma((kt + 1) & 1);
        }
    }

    const float i0 = 1.f / l0r, i1 = 1.f / l1r;
    const int r0g = q0 + warp * 16 + g;
#pragma unroll
    for (int j = 0; j < 16; j++) {
        int col = head * HDIM + j * 8 + 2 * tg;
        uint2 v0 = { f2tf(o[j][0] * i0), f2tf(o[j][1] * i0) };
        uint2 v1 = { f2tf(o[j][2] * i1), f2tf(o[j][3] * i1) };
        *(uint2*)(ctx + ((size_t)r0g * BATCH + bb) * HID + col) = v0;
        *(uint2*)(ctx + ((size_t)(r0g + 8) * BATCH + bb) * HID + col) = v1;
    }
#undef AFULL
#undef AEMPTY
}

// ---------------------------------------------------------------------------
extern "C" void kernel_launch(void* const* d_in, const int* in_sizes, int n_in,
                              void* d_out, int out_size)
{
    const float* hs      = (const float*)d_in[0];
    const float* w_qkv   = (const float*)d_in[2];
    const float* b_qkv   = (const float*)d_in[3];
    const float* w_dense = (const float*)d_in[4];
    const float* b_dense = (const float*)d_in[5];
    float* out = (float*)d_out;

    uint32_t *hs_t, *wqkv_t, *wd_t, *ctx_t, *qkv_buf, *vt_buf;
    cudaGetSymbolAddress((void**)&hs_t, g_hs_t);
    cudaGetSymbolAddress((void**)&wqkv_t, g_wqkv_t);
    cudaGetSymbolAddress((void**)&wd_t, g_wd_t);
    cudaGetSymbolAddress((void**)&qkv_buf, g_qkv);
    cudaGetSymbolAddress((void**)&vt_buf, g_vt);
    cudaGetSymbolAddress((void**)&ctx_t, g_ctx_t);

    cudaFuncSetAttribute(gemm_tf32, cudaFuncAttributeMaxDynamicSharedMemorySize, GEMM_SMEM_BYTES);
    cudaFuncSetAttribute(attn_tf32, cudaFuncAttributeMaxDynamicSharedMemorySize, ATT_BYTES);

    // 0) pre-round GEMM operands to tf32 (rna)
    {
        int n4;
        n4 = ROWS * HID / 4;
        cvt_tf32_kernel<<<(n4 + 255) / 256, 256>>>((const float4*)hs, (uint4*)hs_t, n4);
        n4 = QKV_N * HID / 4;
        cvt_tf32_kernel<<<(n4 + 255) / 256, 256>>>((const float4*)w_qkv, (uint4*)wqkv_t, n4);
        n4 = HID * HID / 4;
        cvt_tf32_kernel<<<(n4 + 255) / 256, 256>>>((const float4*)w_dense, (uint4*)wd_t, n4);
    }

    // 1) QKV projection: qkv(tf32 bits) = hs @ w_qkv^T + b_qkv
    gemm_tf32<<<dim3(QKV_N / GBN, ROWS / GBM), GTHREADS, GEMM_SMEM_BYTES>>>(
        hs_t, wqkv_t, b_qkv, qkv_buf, ROWS, QKV_N, HID, 1, 1);

    // 1b) transpose V -> vt[b][h][hd][S]
    transpose_v<<<dim3(S_LEN / 32, HDIM / 32, BATCH * NHEAD), 256>>>(qkv_buf, vt_buf);

    // 2) causal flash attention -> ctx (tf32 bits)
    attn_tf32<<<dim3(S_LEN / 128, NHEAD, BATCH), 256, ATT_BYTES>>>(qkv_buf, vt_buf, ctx_t);

    // 3) dense projection: out(fp32) = ctx @ w_dense^T (skip_bias_add)
    gemm_tf32<<<dim3(HID / GBN, ROWS / GBM), GTHREADS, GEMM_SMEM_BYTES>>>(
        ctx_t, wd_t, nullptr, (uint32_t*)out, ROWS, HID, HID, 0, 0);

    // 4) b_dense returned separately -> tail of d_out
    if (out_size >= (int)((size_t)ROWS * HID + HID)) {
        cudaMemcpyAsync(out + (size_t)ROWS * HID, b_dense,
                        HID * sizeof(float), cudaMemcpyDeviceToDevice);
    }
}

// round 16
// speedup vs baseline: 1.0204x; 1.0204x over previous
#include <cuda_runtime.h>
#include <math.h>
#include <stdint.h>

#define S_LEN 2048
#define BATCH 2
#define HID 2048
#define NHEAD 16
#define HDIM 128
#define QKV_N 6144
#define ROWS 4096

// ---------------- scratch (device globals; allocation forbidden) -----------
__device__ uint32_t g_hs_t[(size_t)ROWS * HID];      // tf32 bits of hidden_states
__device__ uint32_t g_wqkv_t[(size_t)QKV_N * HID];   // tf32 bits of w_qkv
__device__ uint32_t g_wd_t[(size_t)HID * HID];       // tf32 bits of w_dense
__device__ uint32_t g_qkv[(size_t)ROWS * QKV_N];     // tf32 bits of qkv
__device__ uint32_t g_vt[(size_t)BATCH * NHEAD * HDIM * S_LEN];  // V transposed
__device__ uint32_t g_ctx_t[(size_t)ROWS * HID];     // tf32 bits of ctx

// ---------------- helpers --------------------------------------------------
__device__ __forceinline__ uint32_t f2tf(float x) {
    uint32_t r; asm("cvt.rna.tf32.f32 %0, %1;" : "=r"(r) : "f"(x)); return r;
}
__device__ __forceinline__ float ex2(float x) {
    float y; asm("ex2.approx.f32 %0, %1;" : "=f"(y) : "f"(x)); return y;
}
__device__ __forceinline__ void mma8(float* c, const uint32_t* a, uint32_t b0, uint32_t b1) {
    asm volatile("mma.sync.aligned.m16n8k8.row.col.f32.tf32.tf32.f32 "
        "{%0,%1,%2,%3},{%4,%5,%6,%7},{%8,%9},{%0,%1,%2,%3};"
        : "+f"(c[0]), "+f"(c[1]), "+f"(c[2]), "+f"(c[3])
        : "r"(a[0]), "r"(a[1]), "r"(a[2]), "r"(a[3]), "r"(b0), "r"(b1));
}
__device__ __forceinline__ void ldsm4(uint32_t* r, uint32_t addr) {
    asm volatile("ldmatrix.sync.aligned.m8n8.x4.shared.b16 {%0,%1,%2,%3}, [%4];"
        : "=r"(r[0]), "=r"(r[1]), "=r"(r[2]), "=r"(r[3]) : "r"(addr));
}
__device__ __forceinline__ void cp16(uint32_t saddr, const void* gptr) {
    asm volatile("cp.async.cg.shared.global [%0], [%1], 16;" :: "r"(saddr), "l"(gptr));
}
__device__ __forceinline__ uint32_t smem_u32(const void* p) {
    uint32_t a;
    asm("{ .reg .u64 t; cvta.to.shared.u64 t, %1; cvt.u32.u64 %0, t; }" : "=r"(a) : "l"(p));
    return a;
}

#define MBAR_INIT(addr, cnt) \
    asm volatile("mbarrier.init.shared.b64 [%0], %1;" :: "r"(addr), "r"(cnt) : "memory")
#define MBAR_ARRIVE(addr) \
    asm volatile("mbarrier.arrive.shared.b64 _, [%0];" :: "r"(addr) : "memory")
#define MBAR_ARRIVE_CPASYNC(addr) \
    asm volatile("cp.async.mbarrier.arrive.noinc.shared.b64 [%0];" :: "r"(addr) : "memory")
#define MBAR_WAIT(addr, par) do {                                               \
    uint32_t _done;                                                             \
    asm volatile("{ .reg .pred p; mbarrier.try_wait.parity.acquire.cta.shared::cta.b64 p, [%1], %2; selp.b32 %0,1,0,p; }" \
        : "=r"(_done) : "r"(addr), "r"(par) : "memory");                        \
    while (!_done) {                                                            \
        asm volatile("{ .reg .pred p; mbarrier.try_wait.parity.acquire.cta.shared::cta.b64 p, [%1], %2, 0x989680; selp.b32 %0,1,0,p; }" \
            : "=r"(_done) : "r"(addr), "r"(par) : "memory");                    \
    }                                                                           \
} while (0)

// ---------------- fp32 -> tf32 conversion kernel ---------------------------
__global__ void cvt_tf32_kernel(const float4* __restrict__ in, uint4* __restrict__ out, int n4) {
    int i = blockIdx.x * blockDim.x + threadIdx.x;
    if (i < n4) {
        float4 v = in[i];
        uint4 o;
        o.x = f2tf(v.x); o.y = f2tf(v.y); o.z = f2tf(v.z); o.w = f2tf(v.w);
        out[i] = o;
    }
}

// ---------------- V transpose: qkv V columns -> vt[b][h][hd][S] -------------
__global__ __launch_bounds__(256, 4)
void transpose_v(const uint32_t* __restrict__ qkv, uint32_t* __restrict__ vt)
{
    __shared__ uint32_t tile[32][33];
    const int st = blockIdx.x;
    const int ht = blockIdx.y;
    const int bh = blockIdx.z;
    const int head = bh & 15, bb = bh >> 4;
    const int tx = threadIdx.x & 31, ty = threadIdx.x >> 5;

#pragma unroll
    for (int rr = 0; rr < 4; rr++) {
        int s = st * 32 + ty + rr * 8;
        int hd = ht * 32 + tx;
        tile[ty + rr * 8][tx] =
            qkv[((size_t)s * BATCH + bb) * QKV_N + head * 384 + 2 * HDIM + hd];
    }
    __syncthreads();
#pragma unroll
    for (int rr = 0; rr < 4; rr++) {
        int hd = ht * 32 + ty + rr * 8;
        int s = st * 32 + tx;
        vt[((size_t)(bb * NHEAD + head) * HDIM + hd) * S_LEN + s] = tile[tx][ty + rr * 8];
    }
}

// ---------------- tf32 GEMM (R13 + early empty-arrive) ----------------------
#define GBM 128
#define GBN 128
#define GBK 32
#define SLD 36
#define TSZ (128 * SLD)
#define GEMM_SMEM_BYTES (3 * 2 * TSZ * 4)       // 110592
#define GTHREADS 256

__global__ __launch_bounds__(GTHREADS, 2)
void gemm_tf32(const uint32_t* __restrict__ A, const uint32_t* __restrict__ B,
               const float* __restrict__ bias, uint32_t* __restrict__ C,
               int M, int N, int K, int add_bias, int out_tf32)
{
    extern __shared__ uint32_t sm[];
    __shared__ uint64_t bars[6];

    const int tid = threadIdx.x;
    const int lane = tid & 31, warp = tid >> 5;
    const int g = lane >> 2, tg = lane & 3;
    const int wm = warp >> 2, wn = warp & 3;
    const int m0 = blockIdx.y * GBM, n0 = blockIdx.x * GBN;
    const uint32_t smb = smem_u32(sm);
    const uint32_t barb = smem_u32(bars);
#define FULLB(s)  (barb + 8u * (uint32_t)(s))
#define EMPTYB(s) (barb + 24u + 8u * (uint32_t)(s))

    if (tid == 0) {
#pragma unroll
        for (int s = 0; s < 3; s++) {
            MBAR_INIT(FULLB(s), GTHREADS);
            MBAR_INIT(EMPTYB(s), GTHREADS);
        }
    }
    __syncthreads();

    const uint32_t aRowOff = (uint32_t)(((wm * 64 + (lane & 15)) * SLD + (lane >> 4) * 4) * 4);
    const uint32_t bRowOff = (uint32_t)(((wn * 32 + ((lane >> 4) & 1) * 8 + (lane & 7)) * SLD
                                         + ((lane >> 3) & 1) * 4) * 4);

    float c[4][4][4];
#pragma unroll
    for (int i = 0; i < 4; i++)
#pragma unroll
        for (int j = 0; j < 4; j++)
#pragma unroll
            for (int q = 0; q < 4; q++) c[i][j][q] = 0.f;

    auto load_stage = [&](int it) {
        const int buf = it % 3;
        uint32_t ab = smb + (uint32_t)(buf * 2 * TSZ) * 4;
        uint32_t bb = ab + (uint32_t)TSZ * 4;
        const int k0 = it * GBK;
#pragma unroll
        for (int t = 0; t < 4; t++) {
            int fid = tid + GTHREADS * t;
            int r = fid >> 3, c4 = (fid & 7) * 4;
            cp16(ab + (uint32_t)(r * SLD + c4) * 4, A + (size_t)(m0 + r) * K + k0 + c4);
            cp16(bb + (uint32_t)(r * SLD + c4) * 4, B + (size_t)(n0 + r) * K + k0 + c4);
        }
        MBAR_ARRIVE_CPASYNC(FULLB(buf));
    };

    const int NI = K / GBK;
    load_stage(0);
    load_stage(1);

    for (int it = 0; it < NI; it++) {
        const int nx = it + 2;
        if (nx < NI) {
            const int qn = nx % 3, rn = nx / 3;
            if (rn >= 1) MBAR_WAIT(EMPTYB(qn), (uint32_t)((rn - 1) & 1));
            load_stage(nx);
        }
        const int q = it % 3;
        MBAR_WAIT(FULLB(q), (uint32_t)((it / 3) & 1));

        const uint32_t aBase = smb + (uint32_t)(q * 2 * TSZ) * 4 + aRowOff;
        const uint32_t bBase = smb + (uint32_t)(q * 2 * TSZ + TSZ) * 4 + bRowOff;
#pragma unroll
        for (int kk = 0; kk < 4; kk++) {
            uint32_t a[4][4], bv[2][4];
#pragma unroll
            for (int i = 0; i < 4; i++)
                ldsm4(a[i], aBase + (uint32_t)(i * 16 * SLD) * 4 + kk * 32);
#pragma unroll
            for (int jp = 0; jp < 2; jp++)
                ldsm4(bv[jp], bBase + (uint32_t)(jp * 16 * SLD) * 4 + kk * 32);
            // all smem reads of stage q issued -> release the buffer before
            // the final MMA burst (arrive has release semantics, so the ldsm
            // reads above are ordered before the arrive becomes visible).
            if (kk == 3) MBAR_ARRIVE(EMPTYB(q));
#pragma unroll
            for (int jp = 0; jp < 2; jp++)
#pragma unroll
                for (int i = 0; i < 4; i++) {
                    mma8(c[i][2 * jp],     a[i], bv[jp][0], bv[jp][1]);
                    mma8(c[i][2 * jp + 1], a[i], bv[jp][2], bv[jp][3]);
                }
        }
    }

#pragma unroll
    for (int i = 0; i < 4; i++) {
        int row = m0 + wm * 64 + i * 16 + g;
#pragma unroll
        for (int j = 0; j < 4; j++) {
            int col = n0 + wn * 32 + j * 8 + 2 * tg;
            float b0 = add_bias ? bias[col] : 0.f;
            float b1 = add_bias ? bias[col + 1] : 0.f;
            float v00 = c[i][j][0] + b0, v01 = c[i][j][1] + b1;
            float v10 = c[i][j][2] + b0, v11 = c[i][j][3] + b1;
            uint2 r0, r1;
            if (out_tf32) {
                r0.x = f2tf(v00); r0.y = f2tf(v01);
                r1.x = f2tf(v10); r1.y = f2tf(v11);
            } else {
                r0.x = __float_as_uint(v00); r0.y = __float_as_uint(v01);
                r1.x = __float_as_uint(v10); r1.y = __float_as_uint(v11);
            }
            *(uint2*)(C + (size_t)row * N + col) = r0;
            *(uint2*)(C + (size_t)(row + 8) * N + col) = r1;
        }
    }
#undef FULLB
#undef EMPTYB
}

// ---------------- tf32 flash attention (exact R13 structure) -----------------
#define AQ_LD 132
#define AK_LD 132
#define VT_LD 68
#define AP_LD 68
#define KCH 64
#define KVBUF (KCH * AK_LD + HDIM * VT_LD)      // 17152 words
#define ATT_WORDS (2 * KVBUF + 128 * AP_LD)     // 43008
#define ATT_BYTES (ATT_WORDS * 4)               // 172032

__global__ __launch_bounds__(256, 1)
void attn_tf32(const uint32_t* __restrict__ qkv, const uint32_t* __restrict__ vt,
               uint32_t* __restrict__ ctx)
{
    extern __shared__ uint32_t sm[];
    uint32_t* KV = sm;                           // 2 x KVBUF
    uint32_t* Ps = KV + 2 * KVBUF;
    const uint32_t kvb = smem_u32(KV);
    __shared__ uint64_t abars[4];                // full[0..1], empty[0..1]
    const uint32_t abarb = smem_u32(abars);
#define AFULL(s)  (abarb + 8u * (uint32_t)(s))
#define AEMPTY(s) (abarb + 16u + 8u * (uint32_t)(s))

    const int tid = threadIdx.x, lane = tid & 31, warp = tid >> 5;
    const int g = lane >> 2, tg = lane & 3;
    const int qt = gridDim.x - 1 - blockIdx.x;   // heavy tiles first
    const int head = blockIdx.y, bb = blockIdx.z;
    const int q0 = qt * 128;
    const size_t hoff = (size_t)head * (3 * HDIM);
    const uint32_t* vtp = vt + (size_t)(bb * NHEAD + head) * HDIM * S_LEN;

    if (tid == 0) {
#pragma unroll
        for (int s = 0; s < 2; s++) {
            MBAR_INIT(AFULL(s), 256);
            MBAR_INIT(AEMPTY(s), 256);
        }
    }
    __syncthreads();

    const uint32_t qRowOff = (uint32_t)(((warp * 16 + (lane & 15)) * AQ_LD + (lane >> 4) * 4) * 4);
    const uint32_t kRowOff = (uint32_t)(((((lane >> 4) & 1) * 8 + (lane & 7)) * AK_LD
                                         + ((lane >> 3) & 1) * 4) * 4);
    const uint32_t vRowOff = (uint32_t)(((((lane >> 4) & 1) * 8 + (lane & 7)) * VT_LD
                                         + ((lane >> 3) & 1) * 4) * 4);
    const uint32_t pRowOff = (uint32_t)(((warp * 16 + (lane & 15)) * AP_LD + (lane >> 4) * 4) * 4);
    const uint32_t pBase = smem_u32(Ps) + pRowOff;

    auto load_kv = [&](int kt) {
        const int b = kt & 1;
        const uint32_t kb = kvb + (uint32_t)(b * KVBUF) * 4;
        const uint32_t vb = kb + (uint32_t)(KCH * AK_LD) * 4;
        const int kr0 = kt * KCH;
#pragma unroll
        for (int t = 0; t < 8; t++) {            // K: 64 rows x 32 16B-chunks
            int fid = tid + 256 * t;
            int r = fid >> 5, c4 = (fid & 31) * 4;
            const uint32_t* s = qkv + ((size_t)(kr0 + r) * BATCH + bb) * QKV_N + hoff + HDIM + c4;
            cp16(kb + (uint32_t)(r * AK_LD + c4) * 4, s);
        }
#pragma unroll
        for (int t = 0; t < 8; t++) {            // V^T: 128 rows x 16 chunks
            int fid = tid + 256 * t;
            int r = fid >> 4, c4 = (fid & 15) * 4;
            cp16(vb + (uint32_t)(r * VT_LD + c4) * 4, vtp + (size_t)r * S_LEN + kr0 + c4);
        }
        MBAR_ARRIVE_CPASYNC(AFULL(b));
    };

    // prologue: stage Q into KV buffer 1 (dead after fragment hoist)
    {
        const uint32_t qstage = kvb + (uint32_t)KVBUF * 4;
#pragma unroll
        for (int t = 0; t < 16; t++) {
            int fid = tid + 256 * t;
            int r = fid >> 5, c4 = (fid & 31) * 4;
            const uint32_t* s = qkv + ((size_t)(q0 + r) * BATCH + bb) * QKV_N + hoff + c4;
            cp16(qstage + (uint32_t)(r * AQ_LD + c4) * 4, s);
        }
        asm volatile("cp.async.commit_group;" ::: "memory");
        asm volatile("cp.async.wait_group 0;" ::: "memory");
        __syncthreads();
    }

    uint32_t qf[16][4];
    {
        const uint32_t qBase = kvb + (uint32_t)KVBUF * 4 + qRowOff;
#pragma unroll
        for (int kk = 0; kk < 16; kk++) ldsm4(qf[kk], qBase + kk * 32);
    }
    __syncthreads();                             // all hoists done before buf1 overwrite

    const int nkt = 2 * qt + 2;
    load_kv(0);

    float o[16][4];
#pragma unroll
    for (int j = 0; j < 16; j++)
#pragma unroll
        for (int q = 0; q < 4; q++) o[j][q] = 0.f;
    float m0r = -1e30f, m1r = -1e30f, l0r = 0.f, l1r = 0.f;
    const float scale2 = 0.08838834764831845f * 1.4426950408889634f;
    const float MASK2 = -14426.95f;              // -10000 * log2(e)

    for (int kt = 0; kt < nkt; kt++) {
        if (kt + 1 < nkt) {
            if (kt >= 1) MBAR_WAIT(AEMPTY((kt + 1) & 1), (uint32_t)((((kt + 1) >> 1) - 1) & 1));
            load_kv(kt + 1);
        }
        MBAR_WAIT(AFULL(kt & 1), (uint32_t)((kt >> 1) & 1));

        const int b = kt & 1;
        const uint32_t kBase = kvb + (uint32_t)(b * KVBUF) * 4 + kRowOff;
        const uint32_t vBase = kvb + (uint32_t)(b * KVBUF + KCH * AK_LD) * 4 + vRowOff;
        const int kr0 = kt * KCH;
        const int rowg = q0 + warp * 16 + g;
        const bool active = (kr0 <= q0 + warp * 16 + 15);

        if (active) {
            float s[8][4];
#pragma unroll
            for (int j = 0; j < 8; j++)
#pragma unroll
                for (int q = 0; q < 4; q++) s[j][q] = 0.f;
#pragma unroll
            for (int kk = 0; kk < 16; kk++) {
                uint32_t bv[4][4];
#pragma unroll
                for (int jt = 0; jt < 4; jt++)
                    ldsm4(bv[jt], kBase + (uint32_t)(jt * 16 * AK_LD) * 4 + kk * 32);
#pragma unroll
                for (int jt = 0; jt < 4; jt++) {
                    mma8(s[2 * jt],     qf[kk], bv[jt][0], bv[jt][1]);
                    mma8(s[2 * jt + 1], qf[kk], bv[jt][2], bv[jt][3]);
                }
            }
#pragma unroll
            for (int j = 0; j < 8; j++) {
                int cb = kr0 + j * 8 + 2 * tg;
                s[j][0] = (cb     > rowg)     ? MASK2 : s[j][0] * scale2;
                s[j][1] = (cb + 1 > rowg)     ? MASK2 : s[j][1] * scale2;
                s[j][2] = (cb     > rowg + 8) ? MASK2 : s[j][2] * scale2;
                s[j][3] = (cb + 1 > rowg + 8) ? MASK2 : s[j][3] * scale2;
            }
            {
                float ml = -1e30f;
#pragma unroll
                for (int j = 0; j < 8; j++) ml = fmaxf(ml, fmaxf(s[j][0], s[j][1]));
                ml = fmaxf(ml, __shfl_xor_sync(0xffffffffu, ml, 1));
                ml = fmaxf(ml, __shfl_xor_sync(0xffffffffu, ml, 2));
                float mn = fmaxf(m0r, ml);
                float corr = ex2(m0r - mn);
                float ps = 0.f;
#pragma unroll
                for (int j = 0; j < 8; j++) {
                    s[j][0] = ex2(s[j][0] - mn);
                    s[j][1] = ex2(s[j][1] - mn);
                    ps += s[j][0] + s[j][1];
                }
                ps += __shfl_xor_sync(0xffffffffu, ps, 1);
                ps += __shfl_xor_sync(0xffffffffu, ps, 2);
                l0r = l0r * corr + ps; m0r = mn;
#pragma unroll
                for (int j = 0; j < 16; j++) { o[j][0] *= corr; o[j][1] *= corr; }
            }
            {
                float ml = -1e30f;
#pragma unroll
                for (int j = 0; j < 8; j++) ml = fmaxf(ml, fmaxf(s[j][2], s[j][3]));
                ml = fmaxf(ml, __shfl_xor_sync(0xffffffffu, ml, 1));
                ml = fmaxf(ml, __shfl_xor_sync(0xffffffffu, ml, 2));
                float mn = fmaxf(m1r, ml);
                float corr = ex2(m1r - mn);
                float ps = 0.f;
#pragma unroll
                for (int j = 0; j < 8; j++) {
                    s[j][2] = ex2(s[j][2] - mn);
                    s[j][3] = ex2(s[j][3] - mn);
                    ps += s[j][2] + s[j][3];
                }
                ps += __shfl_xor_sync(0xffffffffu, ps, 1);
                ps += __shfl_xor_sync(0xffffffffu, ps, 2);
                l1r = l1r * corr + ps; m1r = mn;
#pragma unroll
                for (int j = 0; j < 16; j++) { o[j][2] *= corr; o[j][3] *= corr; }
            }
#pragma unroll
            for (int j = 0; j < 8; j++) {
                uint32_t* p0 = Ps + (warp * 16 + g) * AP_LD + j * 8 + 2 * tg;
                uint2 w0 = { f2tf(s[j][0]), f2tf(s[j][1]) };
                uint2 w1 = { f2tf(s[j][2]), f2tf(s[j][3]) };
                *(uint2*)p0 = w0;
                *(uint2*)(p0 + 8 * AP_LD) = w1;
            }
        }
        __syncwarp();
        if (active) {
#pragma unroll
            for (int kk = 0; kk < 8; kk++) {
                uint32_t a[4];
                ldsm4(a, pBase + kk * 32);
#pragma unroll
                for (int jp = 0; jp < 8; jp++) {
                    uint32_t v[4];
                    ldsm4(v, vBase + (uint32_t)(jp * 16 * VT_LD) * 4 + kk * 32);
                    mma8(o[2 * jp],     a, v[0], v[1]);
                    mma8(o[2 * jp + 1], a, v[2], v[3]);
                }
            }
        }
        MBAR_ARRIVE(AEMPTY(kt & 1));
    }

    const float i0 = 1.f / l0r, i1 = 1.f / l1r;
    const int r0g = q0 + warp * 16 + g;
#pragma unroll
    for (int j = 0; j < 16; j++) {
        int col = head * HDIM + j * 8 + 2 * tg;
        uint2 v0 = { f2tf(o[j][0] * i0), f2tf(o[j][1] * i0) };
        uint2 v1 = { f2tf(o[j][2] * i1), f2tf(o[j][3] * i1) };
        *(uint2*)(ctx + ((size_t)r0g * BATCH + bb) * HID + col) = v0;
        *(uint2*)(ctx + ((size_t)(r0g + 8) * BATCH + bb) * HID + col) = v1;
    }
#undef AFULL
#undef AEMPTY
}

// ---------------------------------------------------------------------------
extern "C" void kernel_launch(void* const* d_in, const int* in_sizes, int n_in,
                              void* d_out, int out_size)
{
    const float* hs      = (const float*)d_in[0];
    const float* w_qkv   = (const float*)d_in[2];
    const float* b_qkv   = (const float*)d_in[3];
    const float* w_dense = (const float*)d_in[4];
    const float* b_dense = (const float*)d_in[5];
    float* out = (float*)d_out;

    uint32_t *hs_t, *wqkv_t, *wd_t, *ctx_t, *qkv_buf, *vt_buf;
    cudaGetSymbolAddress((void**)&hs_t, g_hs_t);
    cudaGetSymbolAddress((void**)&wqkv_t, g_wqkv_t);
    cudaGetSymbolAddress((void**)&wd_t, g_wd_t);
    cudaGetSymbolAddress((void**)&qkv_buf, g_qkv);
    cudaGetSymbolAddress((void**)&vt_buf, g_vt);
    cudaGetSymbolAddress((void**)&ctx_t, g_ctx_t);

    cudaFuncSetAttribute(gemm_tf32, cudaFuncAttributeMaxDynamicSharedMemorySize, GEMM_SMEM_BYTES);
    cudaFuncSetAttribute(attn_tf32, cudaFuncAttributeMaxDynamicSharedMemorySize, ATT_BYTES);

    // 0) pre-round GEMM operands to tf32 (rna)
    {
        int n4;
        n4 = ROWS * HID / 4;
        cvt_tf32_kernel<<<(n4 + 255) / 256, 256>>>((const float4*)hs, (uint4*)hs_t, n4);
        n4 = QKV_N * HID / 4;
        cvt_tf32_kernel<<<(n4 + 255) / 256, 256>>>((const float4*)w_qkv, (uint4*)wqkv_t, n4);
        n4 = HID * HID / 4;
        cvt_tf32_kernel<<<(n4 + 255) / 256, 256>>>((const float4*)w_dense, (uint4*)wd_t, n4);
    }

    // 1) QKV projection: qkv(tf32 bits) = hs @ w_qkv^T + b_qkv
    gemm_tf32<<<dim3(QKV_N / GBN, ROWS / GBM), GTHREADS, GEMM_SMEM_BYTES>>>(
        hs_t, wqkv_t, b_qkv, qkv_buf, ROWS, QKV_N, HID, 1, 1);

    // 1b) transpose V -> vt[b][h][hd][S]
    transpose_v<<<dim3(S_LEN / 32, HDIM / 32, BATCH * NHEAD), 256>>>(qkv_buf, vt_buf);

    // 2) causal flash attention -> ctx (tf32 bits)
    attn_tf32<<<dim3(S_LEN / 128, NHEAD, BATCH), 256, ATT_BYTES>>>(qkv_buf, vt_buf, ctx_t);

    // 3) dense projection: out(fp32) = ctx @ w_dense^T (skip_bias_add)
    gemm_tf32<<<dim3(HID / GBN, ROWS / GBM), GTHREADS, GEMM_SMEM_BYTES>>>(
        ctx_t, wd_t, nullptr, (uint32_t*)out, ROWS, HID, HID, 0, 0);

    // 4) b_dense returned separately -> tail of d_out
    if (out_size >= (int)((size_t)ROWS * HID + HID)) {
        cudaMemcpyAsync(out + (size_t)ROWS * HID, b_dense,
                        HID * sizeof(float), cudaMemcpyDeviceToDevice);
    }
}